// round 5
// baseline (speedup 1.0000x reference)
#include <cuda_runtime.h>
#include <cuda_fp16.h>
#include <cstdint>

#define Nn 8
#define Cc 128
#define Ll 1024
#define Kk 100
#define EPSf 1e-8f

// Normalized fp16 rows, [N, L, C] (256B per row).
__device__ __half g_zh[Nn * Ll * Cc];
__device__ __half g_ch[Nn * Ll * Cc];

// Fused: transpose + norm + normalize + fp16 convert, one pass over the input.
// grid = (L/32, 2N). blockIdx.y: first N = z [N,C,L], next N = c [N,C,L+1] (cols 1..L).
// Block: 256 threads. Loads a [C=128, T=32] fp32 tile, computes per-t rnorm,
// writes 32 normalized fp16 rows of 128 channels each.
__global__ void __launch_bounds__(256) prep_k(const float* __restrict__ zsrc,
                                              const float* __restrict__ csrc) {
    __shared__ float tile[32][129];   // [t][ch], pad to kill bank conflicts
    __shared__ float sp[8][32];
    __shared__ float srn[32];

    int zz = blockIdx.y;
    bool is_c = zz >= Nn;
    int n = is_c ? zz - Nn : zz;
    int ld      = is_c ? (Ll + 1) : Ll;
    int col_off = is_c ? 1 : 0;
    int t0 = blockIdx.x * 32;
    const float* s = (is_c ? csrc : zsrc) + (size_t)n * Cc * ld + col_off + t0;
    __half* d = (is_c ? g_ch : g_zh) + ((size_t)n * Ll + t0) * Cc;

    int tid = threadIdx.x;
    int tx  = tid & 31;    // t within tile
    int ty  = tid >> 5;    // 0..7

    // Load: 128 rows x 32 t, coalesced over t (lane -> t).
#pragma unroll
    for (int i = 0; i < 16; i++) {
        int ch = i * 8 + ty;
        tile[tx][ch] = s[(size_t)ch * ld + tx];
    }
    __syncthreads();

    // Per-t sum of squares: thread (tx,ty) covers 16 channels of row tx.
    float acc = 0.f;
#pragma unroll
    for (int i = 0; i < 16; i++) {
        float v = tile[tx][ty * 16 + i];
        acc += v * v;
    }
    sp[ty][tx] = acc;
    __syncthreads();
    if (tid < 32) {
        float sum = 0.f;
#pragma unroll
        for (int y = 0; y < 8; y++) sum += sp[y][tid];
        srn[tid] = 1.0f / fmaxf(sqrtf(sum), EPSf);
    }
    __syncthreads();

    // Write: 32 rows x 16 uint4 (8 halves each) = 512 uint4; 2 per thread,
    // consecutive tid -> consecutive 16B chunks (fully coalesced).
#pragma unroll
    for (int i = 0; i < 2; i++) {
        int linear = tid + i * 256;
        int t = linear >> 4;        // row within tile
        int k = linear & 15;        // uint4 within row
        float rn = srn[t];
        __half2 h[4];
#pragma unroll
        for (int q = 0; q < 4; q++) {
            float a = tile[t][k * 8 + 2 * q]     * rn;
            float b = tile[t][k * 8 + 2 * q + 1] * rn;
            h[q] = __floats2half2_rn(a, b);
        }
        ((uint4*)(d + (size_t)t * Cc))[k] = *(const uint4*)h;
    }
}

// Warp-per-row. 8 lanes per dot (lane owns 16 channels = 2 uint4 of half),
// 4 dots per pass, 26 passes. Double-buffered gather.
__global__ void __launch_bounds__(256) main_k(const int* __restrict__ neg_inds,
                                              float* __restrict__ out) {
    int warp = threadIdx.x >> 5;
    int r    = (blockIdx.x << 3) + warp;   // 0..N*L-1
    int n    = r >> 10;
    int t    = r & (Ll - 1);
    int lane = threadIdx.x & 31;
    int g    = lane >> 3;                  // dot slot within pass
    int p    = lane & 7;                   // lane within dot

    // c chunk: 16 channels for this lane, converted to fp32 once.
    const uint4* crow = (const uint4*)(g_ch + (size_t)r * Cc);
    uint4 ca = crow[2 * p], cb = crow[2 * p + 1];
    float2 cf[8];
    {
        const __half2* h;
        h = (const __half2*)&ca;
        cf[0] = __half22float2(h[0]); cf[1] = __half22float2(h[1]);
        cf[2] = __half22float2(h[2]); cf[3] = __half22float2(h[3]);
        h = (const __half2*)&cb;
        cf[4] = __half22float2(h[0]); cf[5] = __half22float2(h[1]);
        cf[6] = __half22float2(h[2]); cf[7] = __half22float2(h[3]);
    }

    const uint4* zbase = (const uint4*)(g_zh + ((size_t)n << 10) * Cc);
    const int*   ni    = neg_inds + (size_t)r * Kk;
    float*       orow  = out + (size_t)r * (Kk + 1);

    // Prologue: fetch slot j = g for pass 0.
    int idx = (g == 0) ? t : ni[g - 1];
    uint4 z0 = zbase[(size_t)idx * 16 + 2 * p];
    uint4 z1 = zbase[(size_t)idx * 16 + 2 * p + 1];

#pragma unroll
    for (int pass = 0; pass < 26; pass++) {
        int j = pass * 4 + g;

        // Prefetch next pass (slots j+4 are never the positive).
        uint4 y0, y1;
        if (pass < 25) {
            int jn   = j + 4;
            int idxn = (jn <= Kk) ? ni[jn - 1] : t;
            y0 = zbase[(size_t)idxn * 16 + 2 * p];
            y1 = zbase[(size_t)idxn * 16 + 2 * p + 1];
        }

        float a = 0.f, b = 0.f;
        {
            const __half2* h = (const __half2*)&z0;
#pragma unroll
            for (int q = 0; q < 4; q++) {
                float2 zf = __half22float2(h[q]);
                a = fmaf(cf[q].x, zf.x, a);
                b = fmaf(cf[q].y, zf.y, b);
            }
            h = (const __half2*)&z1;
#pragma unroll
            for (int q = 0; q < 4; q++) {
                float2 zf = __half22float2(h[q]);
                a = fmaf(cf[4 + q].x, zf.x, a);
                b = fmaf(cf[4 + q].y, zf.y, b);
            }
        }
        a += b;

        a += __shfl_xor_sync(0xffffffffu, a, 1);
        a += __shfl_xor_sync(0xffffffffu, a, 2);
        a += __shfl_xor_sync(0xffffffffu, a, 4);

        if (p == 0 && j <= Kk)
            orow[j] = a * 2.0f;   // norms folded in; / TEMP = *2

        z0 = y0; z1 = y1;
    }
}

extern "C" void kernel_launch(void* const* d_in, const int* in_sizes, int n_in,
                              void* d_out, int out_size) {
    const float* z  = (const float*)d_in[0];  // [N, C, L]
    const float* c  = (const float*)d_in[1];  // [N, C, L+1]
    const int*   ni = (const int*)d_in[2];    // [N, L, K]
    float* out = (float*)d_out;               // [N*L, K+1]

    dim3 pg(Ll / 32, 2 * Nn);
    prep_k<<<pg, 256>>>(z, c);

    main_k<<<(Nn * Ll) / 8, 256>>>(ni, out);
}

// round 6
// speedup vs baseline: 1.8008x; 1.8008x over previous
#include <cuda_runtime.h>
#include <cuda_fp16.h>
#include <cstdint>

#define Nn 8
#define Cc 128
#define Ll 1024
#define Kk 100
#define EPSf 1e-8f

// Normalized fp16 rows, [N, L, C] (256B per row).
__device__ __half g_zh[Nn * Ll * Cc];
__device__ __half g_ch[Nn * Ll * Cc];

// Fused: transpose + norm + normalize + fp16 convert, one pass over the input.
// grid = (L/32, 2N). blockIdx.y: first N = z [N,C,L], next N = c [N,C,L+1] (cols 1..L).
__global__ void __launch_bounds__(256) prep_k(const float* __restrict__ zsrc,
                                              const float* __restrict__ csrc) {
    __shared__ float tile[32][129];   // [t][ch], pad to kill bank conflicts
    __shared__ float sp[8][32];
    __shared__ float srn[32];

    int zz = blockIdx.y;
    bool is_c = zz >= Nn;
    int n = is_c ? zz - Nn : zz;
    int ld      = is_c ? (Ll + 1) : Ll;
    int col_off = is_c ? 1 : 0;
    int t0 = blockIdx.x * 32;
    const float* s = (is_c ? csrc : zsrc) + (size_t)n * Cc * ld + col_off + t0;
    __half* d = (is_c ? g_ch : g_zh) + ((size_t)n * Ll + t0) * Cc;

    int tid = threadIdx.x;
    int tx  = tid & 31;    // t within tile
    int ty  = tid >> 5;    // 0..7

    // Load: 128 rows x 32 t, coalesced over t (lane -> t).
#pragma unroll
    for (int i = 0; i < 16; i++) {
        int ch = i * 8 + ty;
        tile[tx][ch] = s[(size_t)ch * ld + tx];
    }
    __syncthreads();

    // Per-t sum of squares: thread (tx,ty) covers 16 channels of row tx.
    float acc = 0.f;
#pragma unroll
    for (int i = 0; i < 16; i++) {
        float v = tile[tx][ty * 16 + i];
        acc += v * v;
    }
    sp[ty][tx] = acc;
    __syncthreads();
    if (tid < 32) {
        float sum = 0.f;
#pragma unroll
        for (int y = 0; y < 8; y++) sum += sp[y][tid];
        srn[tid] = 1.0f / fmaxf(sqrtf(sum), EPSf);
    }
    __syncthreads();

    // Write: 32 rows x 16 uint4; 2 per thread, consecutive tid -> consecutive
    // 16B chunks (fully coalesced).
#pragma unroll
    for (int i = 0; i < 2; i++) {
        int linear = tid + i * 256;
        int t = linear >> 4;        // row within tile
        int k = linear & 15;        // uint4 within row
        float rn = srn[t];
        __half2 h[4];
#pragma unroll
        for (int q = 0; q < 4; q++) {
            float a = tile[t][k * 8 + 2 * q]     * rn;
            float b = tile[t][k * 8 + 2 * q + 1] * rn;
            h[q] = __floats2half2_rn(a, b);
        }
        ((uint4*)(d + (size_t)t * Cc))[k] = *(const uint4*)h;
    }
}

// Warp-per-row. 8 lanes per dot; lane p owns uint4 slots p and 8+p so each
// 8-lane group's LDG.128 is one contiguous 128B line (minimal L1 wavefronts).
// 4 dots per pass, 26 passes. Double-buffered gather.
__global__ void __launch_bounds__(256) main_k(const int* __restrict__ neg_inds,
                                              float* __restrict__ out) {
    int warp = threadIdx.x >> 5;
    int r    = (blockIdx.x << 3) + warp;   // 0..N*L-1
    int n    = r >> 10;
    int t    = r & (Ll - 1);
    int lane = threadIdx.x & 31;
    int g    = lane >> 3;                  // dot slot within pass
    int p    = lane & 7;                   // lane within dot

    // c chunk: 16 channels for this lane (slots p and 8+p), fp32 once.
    const uint4* crow = (const uint4*)(g_ch + (size_t)r * Cc);
    uint4 ca = crow[p], cb = crow[8 + p];
    float2 cf[8];
    {
        const __half2* h;
        h = (const __half2*)&ca;
        cf[0] = __half22float2(h[0]); cf[1] = __half22float2(h[1]);
        cf[2] = __half22float2(h[2]); cf[3] = __half22float2(h[3]);
        h = (const __half2*)&cb;
        cf[4] = __half22float2(h[0]); cf[5] = __half22float2(h[1]);
        cf[6] = __half22float2(h[2]); cf[7] = __half22float2(h[3]);
    }

    const uint4* zbase = (const uint4*)(g_zh + ((size_t)n << 10) * Cc);
    const int*   ni    = neg_inds + (size_t)r * Kk;
    float*       orow  = out + (size_t)r * (Kk + 1);

    // Prologue: fetch slot j = g for pass 0.
    int idx = (g == 0) ? t : ni[g - 1];
    uint4 z0 = zbase[(size_t)idx * 16 + p];
    uint4 z1 = zbase[(size_t)idx * 16 + 8 + p];

#pragma unroll
    for (int pass = 0; pass < 26; pass++) {
        int j = pass * 4 + g;

        // Prefetch next pass (slots j+4 are never the positive).
        uint4 y0, y1;
        if (pass < 25) {
            int jn   = j + 4;
            int idxn = (jn <= Kk) ? ni[jn - 1] : t;
            y0 = zbase[(size_t)idxn * 16 + p];
            y1 = zbase[(size_t)idxn * 16 + 8 + p];
        }

        float a = 0.f, b = 0.f;
        {
            const __half2* h = (const __half2*)&z0;
#pragma unroll
            for (int q = 0; q < 4; q++) {
                float2 zf = __half22float2(h[q]);
                a = fmaf(cf[q].x, zf.x, a);
                b = fmaf(cf[q].y, zf.y, b);
            }
            h = (const __half2*)&z1;
#pragma unroll
            for (int q = 0; q < 4; q++) {
                float2 zf = __half22float2(h[q]);
                a = fmaf(cf[4 + q].x, zf.x, a);
                b = fmaf(cf[4 + q].y, zf.y, b);
            }
        }
        a += b;

        a += __shfl_xor_sync(0xffffffffu, a, 1);
        a += __shfl_xor_sync(0xffffffffu, a, 2);
        a += __shfl_xor_sync(0xffffffffu, a, 4);

        if (p == 0 && j <= Kk)
            orow[j] = a * 2.0f;   // norms folded in; / TEMP = *2

        z0 = y0; z1 = y1;
    }
}

extern "C" void kernel_launch(void* const* d_in, const int* in_sizes, int n_in,
                              void* d_out, int out_size) {
    const float* z  = (const float*)d_in[0];  // [N, C, L]
    const float* c  = (const float*)d_in[1];  // [N, C, L+1]
    const int*   ni = (const int*)d_in[2];    // [N, L, K]
    float* out = (float*)d_out;               // [N*L, K+1]

    dim3 pg(Ll / 32, 2 * Nn);
    prep_k<<<pg, 256>>>(z, c);

    main_k<<<(Nn * Ll) / 8, 256>>>(ni, out);
}